// round 4
// baseline (speedup 1.0000x reference)
#include <cuda_runtime.h>
#include <cuda_bf16.h>
#include <limits.h>

#define B     8
#define NN    1024
#define EE    1536
#define FIN   64
#define FOUT  64
#define FEDGE 32

// ---------------- scratch (static device globals; no allocation) ------------
// Endpoint encoding: g_pmax[e] = max(i)+1, g_pmin[e] = NN - min(i).
// Zero-init means "unset"; atomicMax with the same values every replay is
// idempotent -> no per-launch reset kernel needed, fully deterministic.
__device__ int   g_pmin[EE];
__device__ int   g_pmax[EE];
__device__ float g_lw[EE];          // lap[src,dst] per edge
__device__ float g_lapii[NN];       // lap diagonal
__device__ float g_ew[B * EE];      // edge scalar weights
__device__ float g_S[B * NN];       // sum of ew over edges incident to node
__device__ float g_h[B * NN * FOUT];// nodes @ W

// K1: recover edge endpoints from incidence matrix (coalesced float4 sweep),
//     plus fold in the old init work: zero g_S, gather lap diagonal.
__global__ void k_scan(const float4* __restrict__ inc4,
                       const float* __restrict__ lap) {
    int t = blockIdx.x * blockDim.x + threadIdx.x;   // NN*EE/4 threads
    float4 v = inc4[t];
    int base = t * 4;
    int i = base / EE;
    int e = base % EE;
    if (v.x != 0.0f) { atomicMax(&g_pmax[e + 0], i + 1); atomicMax(&g_pmin[e + 0], NN - i); }
    if (v.y != 0.0f) { atomicMax(&g_pmax[e + 1], i + 1); atomicMax(&g_pmin[e + 1], NN - i); }
    if (v.z != 0.0f) { atomicMax(&g_pmax[e + 2], i + 1); atomicMax(&g_pmin[e + 2], NN - i); }
    if (v.w != 0.0f) { atomicMax(&g_pmax[e + 3], i + 1); atomicMax(&g_pmin[e + 3], NN - i); }

    // block 0 does the tiny init work (consumed only by later kernels)
    if (blockIdx.x == 0) {
        int tid = threadIdx.x;
        #pragma unroll
        for (int j = 0; j < (B * NN) / 256; j++) g_S[tid + j * 256] = 0.0f;
        #pragma unroll
        for (int j = 0; j < NN / 256; j++) {
            int n = tid + j * 256;
            g_lapii[n] = lap[n * NN + n];
        }
    }
}

// K2: ew[b,e] = edges[b,e,:] . evec ; accumulate S at both endpoints; gather lap edge value
__global__ void k_edge(const float* __restrict__ edges,
                       const float* __restrict__ evec,
                       const float* __restrict__ lap) {
    int gw   = (blockIdx.x * blockDim.x + threadIdx.x) >> 5;  // warp per (b,e)
    int lane = threadIdx.x & 31;
    if (gw >= B * EE) return;
    int b = gw / EE, e = gw - b * EE;

    float x = edges[gw * FEDGE + lane] * evec[lane];
    #pragma unroll
    for (int o = 16; o; o >>= 1) x += __shfl_xor_sync(0xffffffffu, x, o);

    if (lane == 0) {
        int s = NN - g_pmin[e];
        int d = g_pmax[e] - 1;
        g_ew[gw] = x;
        atomicAdd(&g_S[b * NN + s], x);
        atomicAdd(&g_S[b * NN + d], x);
        if (b == 0) g_lw[e] = lap[s * NN + d];
    }
}

// K3: h = nodes @ W with register tiling, fused diagonal output term.
// Block: 128 threads, 32 rows x 64 cols. Thread: 2 rows x 8 cols (4x float4 accs).
// grid 256; 8 blocks/SM warp-limit -> 32 warps/SM; FFMA:LDS = 16:4 per k-iter.
#define XPAD 68
__global__ void __launch_bounds__(128) k_gemm_diag(const float* __restrict__ nodes,
                                                   const float* __restrict__ W,
                                                   float* __restrict__ out) {
    __shared__ float4 sW4[FIN][FOUT / 4];   // 16 KB
    __shared__ float  sX[32][XPAD];         // ~8.5 KB

    int tid = threadIdx.x;                  // 128
    int blk = blockIdx.x;                   // 0..255, 32 rows each
    int R0  = blk * 32;

    // fill W tile: 1024 float4, 8 per thread (coalesced)
    const float4* W4 = (const float4*)W;
    #pragma unroll
    for (int i = 0; i < 8; i++) {
        int idx = tid + i * 128;            // 0..1023
        sW4[idx >> 4][idx & 15] = W4[idx];
    }
    // fill X tile: 32 rows x 64 floats = 512 float4, 4 per thread
    const float4* X4 = (const float4*)(nodes + (size_t)R0 * FIN);
    #pragma unroll
    for (int i = 0; i < 4; i++) {
        int idx = tid + i * 128;            // 0..511
        float4 v = X4[idx];
        int row = idx >> 4, c4 = (idx & 15) * 4;
        sX[row][c4 + 0] = v.x; sX[row][c4 + 1] = v.y;
        sX[row][c4 + 2] = v.z; sX[row][c4 + 3] = v.w;
    }
    __syncthreads();

    int tx = tid & 7;         // col group: cols tx*8 .. tx*8+7 (two float4s)
    int ty = tid >> 3;        // row group 0..15: rows ty*2, ty*2+1

    float4 a00 = make_float4(0.f,0.f,0.f,0.f), a01 = make_float4(0.f,0.f,0.f,0.f);
    float4 a10 = make_float4(0.f,0.f,0.f,0.f), a11 = make_float4(0.f,0.f,0.f,0.f);

    #pragma unroll
    for (int k = 0; k < FIN; k++) {
        float4 w0 = sW4[k][tx * 2 + 0];
        float4 w1 = sW4[k][tx * 2 + 1];
        float  x0 = sX[ty * 2 + 0][k];
        float  x1 = sX[ty * 2 + 1][k];
        a00.x += x0 * w0.x; a00.y += x0 * w0.y; a00.z += x0 * w0.z; a00.w += x0 * w0.w;
        a01.x += x0 * w1.x; a01.y += x0 * w1.y; a01.z += x0 * w1.z; a01.w += x0 * w1.w;
        a10.x += x1 * w0.x; a10.y += x1 * w0.y; a10.z += x1 * w0.z; a10.w += x1 * w0.w;
        a11.x += x1 * w1.x; a11.y += x1 * w1.y; a11.z += x1 * w1.z; a11.w += x1 * w1.w;
    }

    int r0 = R0 + ty * 2;
    float d0 = g_lapii[r0 & (NN - 1)]       * g_S[r0];
    float d1 = g_lapii[(r0 + 1) & (NN - 1)] * g_S[r0 + 1];

    float4* gh4 = (float4*)g_h;
    float4* go4 = (float4*)out;
    int o0 = r0 * (FOUT / 4) + tx * 2;
    int o1 = o0 + (FOUT / 4);

    gh4[o0]     = a00;
    gh4[o0 + 1] = a01;
    gh4[o1]     = a10;
    gh4[o1 + 1] = a11;
    go4[o0]     = make_float4(d0*a00.x, d0*a00.y, d0*a00.z, d0*a00.w);
    go4[o0 + 1] = make_float4(d0*a01.x, d0*a01.y, d0*a01.z, d0*a01.w);
    go4[o1]     = make_float4(d1*a10.x, d1*a10.y, d1*a10.z, d1*a10.w);
    go4[o1 + 1] = make_float4(d1*a11.x, d1*a11.y, d1*a11.z, d1*a11.w);
}

// vectorized fp32 reduction into global memory (sm_90+)
__device__ __forceinline__ void red_add_v4(float* p, float4 v) {
    asm volatile("red.global.add.v4.f32 [%0], {%1, %2, %3, %4};"
                 :: "l"(p), "f"(v.x), "f"(v.y), "f"(v.z), "f"(v.w)
                 : "memory");
}

// K4: scatter off-diagonal edge contributions with v4 REDs.
//     warp per (b,e); lanes 0-15 handle dst->src row, lanes 16-31 src->dst row.
__global__ void k_scatter(float* __restrict__ out) {
    int gw   = (blockIdx.x * blockDim.x + threadIdx.x) >> 5;
    int lane = threadIdx.x & 31;
    if (gw >= B * EE) return;
    int b = gw / EE, e = gw - b * EE;

    float val = g_ew[gw] * g_lw[e];
    int s = NN - g_pmin[e];
    int d = g_pmax[e] - 1;

    const float4* hs = (const float4*)(g_h + (size_t)(b * NN + s) * FOUT);
    const float4* hd = (const float4*)(g_h + (size_t)(b * NN + d) * FOUT);
    float* os = out + (size_t)(b * NN + s) * FOUT;
    float* od = out + (size_t)(b * NN + d) * FOUT;

    if (lane < 16) {
        // os += val * hd   (16 lanes x float4 = 64 cols)
        float4 hv = hd[lane];
        red_add_v4(os + lane * 4,
                   make_float4(val*hv.x, val*hv.y, val*hv.z, val*hv.w));
    } else {
        int l = lane - 16;
        float4 hv = hs[l];
        red_add_v4(od + l * 4,
                   make_float4(val*hv.x, val*hv.y, val*hv.z, val*hv.w));
    }
}

extern "C" void kernel_launch(void* const* d_in, const int* in_sizes, int n_in,
                              void* d_out, int out_size) {
    const float* nodes = (const float*)d_in[0];   // [B,N,FIN]
    const float* edges = (const float*)d_in[1];   // [B,E,FEDGE]
    const float* W     = (const float*)d_in[2];   // [FIN,FOUT]
    const float* evec  = (const float*)d_in[3];   // [FEDGE]
    const float* inc   = (const float*)d_in[4];   // [N,E]
    const float* lap   = (const float*)d_in[5];   // [N,N]
    float* out = (float*)d_out;                   // [B,N,FOUT]

    k_scan<<<(NN * EE / 4) / 256, 256>>>((const float4*)inc, lap);
    k_edge<<<(B * EE * 32) / 256, 256>>>(edges, evec, lap);
    k_gemm_diag<<<(B * NN) / 32, 128>>>(nodes, W, out);
    k_scatter<<<(B * EE * 32) / 256, 256>>>(out);
}